// round 6
// baseline (speedup 1.0000x reference)
#include <cuda_runtime.h>
#include <cstdint>

#define NMAX 150016
#define EMAX 2400000

__device__ int   g_src[EMAX];
__device__ int   g_dst[EMAX];
__device__ int   g_degi[NMAX];
__device__ float g_dis[NMAX];
__device__ __align__(16) float g_buf0[NMAX * 32];   // h' (scaled GEMM output)
__device__ __align__(16) float g_buf1[NMAX * 32];   // layer-1 aggregate
__device__ __align__(16) float g_buf2[NMAX * 32];   // layer-2 aggregate
__device__ float g_h3[NMAX];
__device__ float g_acc3[NMAX];

// ---------------------------------------------------------------- prep kernels

__global__ void deg_init_k(int N) {
    int i = blockIdx.x * blockDim.x + threadIdx.x;
    if (i < N) g_degi[i] = 1;  // self-loop
}

// edge_index is int32 (JAX x64 disabled: jnp.int64 request -> int32).
// Bounds-guard: invalid edges become self-referencing no-ops instead of traps.
__global__ void edge_pre_k(const int* __restrict__ ei, int E, int N) {
    int e = blockIdx.x * blockDim.x + threadIdx.x;
    if (e >= E) return;
    int s = ei[e];
    int d = ei[E + e];
    if ((unsigned)s >= (unsigned)N) s = 0;
    if ((unsigned)d >= (unsigned)N) d = 0;
    g_src[e] = s;
    g_dst[e] = d;
    atomicAdd(&g_degi[d], 1);
}

__global__ void dis_k(int N) {
    int i = blockIdx.x * blockDim.x + threadIdx.x;
    if (i < N) g_dis[i] = rsqrtf((float)g_degi[i]);
}

// ---------------------------------------------------------------- GEMM (N=32 out cols)
// Block: 32 rows x 32 cols, 64 threads, 4x4 microtile per thread.
// PRE: input transform relu(dis[row]*v + bias[col])  (fuses previous layer's epilogue)
// Epilogue: multiply row by dis[row]  (produces h' = h * dis[src] directly)

template <int K, bool PRE>
__global__ void __launch_bounds__(64) gemm_k(
    const float* __restrict__ A, const float* __restrict__ W,
    const float* __restrict__ dis, const float* __restrict__ bias,
    float* __restrict__ out, int M)
{
    constexpr int BR = 32;
    __shared__ float xs[BR][K + 1];
    __shared__ float ws[K][32];

    const int tid  = threadIdx.x;
    const int row0 = blockIdx.x * BR;

    // stage W: K*32 floats = K*8 float4
    for (int i = tid; i < K * 8; i += 64)
        ((float4*)ws)[i] = ((const float4*)W)[i];

    // stage X tile (with optional fused relu(dis*v + b))
    for (int i = tid; i < BR * K / 4; i += 64) {
        int r = (i * 4) / K, c = (i * 4) % K;
        int row = row0 + r;
        float4 v = make_float4(0.f, 0.f, 0.f, 0.f);
        if (row < M) {
            v = *(const float4*)(A + (size_t)row * K + c);
            if (PRE) {
                float dd  = dis[row];
                float4 bb = *(const float4*)(bias + c);
                v.x = fmaxf(fmaf(dd, v.x, bb.x), 0.f);
                v.y = fmaxf(fmaf(dd, v.y, bb.y), 0.f);
                v.z = fmaxf(fmaf(dd, v.z, bb.z), 0.f);
                v.w = fmaxf(fmaf(dd, v.w, bb.w), 0.f);
            }
        }
        xs[r][c + 0] = v.x;
        xs[r][c + 1] = v.y;
        xs[r][c + 2] = v.z;
        xs[r][c + 3] = v.w;
    }
    __syncthreads();

    const int tx = tid & 7;    // col quad: cols 4*tx .. 4*tx+3
    const int ty = tid >> 3;   // row quad: rows 4*ty .. 4*ty+3

    float acc[4][4] = {};
#pragma unroll 8
    for (int k = 0; k < K; ++k) {
        float4 wv = *(const float4*)&ws[k][4 * tx];
        float xr0 = xs[4 * ty + 0][k];
        float xr1 = xs[4 * ty + 1][k];
        float xr2 = xs[4 * ty + 2][k];
        float xr3 = xs[4 * ty + 3][k];
        acc[0][0] = fmaf(xr0, wv.x, acc[0][0]);
        acc[0][1] = fmaf(xr0, wv.y, acc[0][1]);
        acc[0][2] = fmaf(xr0, wv.z, acc[0][2]);
        acc[0][3] = fmaf(xr0, wv.w, acc[0][3]);
        acc[1][0] = fmaf(xr1, wv.x, acc[1][0]);
        acc[1][1] = fmaf(xr1, wv.y, acc[1][1]);
        acc[1][2] = fmaf(xr1, wv.z, acc[1][2]);
        acc[1][3] = fmaf(xr1, wv.w, acc[1][3]);
        acc[2][0] = fmaf(xr2, wv.x, acc[2][0]);
        acc[2][1] = fmaf(xr2, wv.y, acc[2][1]);
        acc[2][2] = fmaf(xr2, wv.z, acc[2][2]);
        acc[2][3] = fmaf(xr2, wv.w, acc[2][3]);
        acc[3][0] = fmaf(xr3, wv.x, acc[3][0]);
        acc[3][1] = fmaf(xr3, wv.y, acc[3][1]);
        acc[3][2] = fmaf(xr3, wv.z, acc[3][2]);
        acc[3][3] = fmaf(xr3, wv.w, acc[3][3]);
    }

#pragma unroll
    for (int i = 0; i < 4; ++i) {
        int row = row0 + 4 * ty + i;
        if (row < M) {
            float d = dis[row];
            float4 o = make_float4(acc[i][0] * d, acc[i][1] * d,
                                   acc[i][2] * d, acc[i][3] * d);
            *(float4*)(out + (size_t)row * 32 + 4 * tx) = o;
        }
    }
}

// ---------------------------------------------------------------- copies (acc init = self loop term h')

__global__ void copy01_k(int n4) {
    int i = blockIdx.x * blockDim.x + threadIdx.x;
    if (i < n4) ((float4*)g_buf1)[i] = ((const float4*)g_buf0)[i];
}
__global__ void copy02_k(int n4) {
    int i = blockIdx.x * blockDim.x + threadIdx.x;
    if (i < n4) ((float4*)g_buf2)[i] = ((const float4*)g_buf0)[i];
}
__global__ void copy3_k(int N) {
    int i = blockIdx.x * blockDim.x + threadIdx.x;
    if (i < N) g_acc3[i] = g_h3[i];
}

// ---------------------------------------------------------------- edge scatter
// 8 threads per edge (float4 quads). Gather h'[src] via LDG.128 (L2-resident),
// then 4 scalar RED.ADD.F32 to acc[dst].

__global__ void scatter_k(const float* __restrict__ h, float* __restrict__ acc, int E) {
    int t = blockIdx.x * blockDim.x + threadIdx.x;
    int e = t >> 3;
    if (e >= E) return;
    int q = t & 7;
    int s = __ldg(&g_src[e]);
    int d = __ldg(&g_dst[e]);
    float4 v = *(const float4*)(h + (size_t)s * 32 + q * 4);
    float* p = acc + (size_t)d * 32 + q * 4;
    atomicAdd(p + 0, v.x);
    atomicAdd(p + 1, v.y);
    atomicAdd(p + 2, v.z);
    atomicAdd(p + 3, v.w);
}

__global__ void scatter3_k(int E) {
    int e = blockIdx.x * blockDim.x + threadIdx.x;
    if (e >= E) return;
    int s = __ldg(&g_src[e]);
    int d = __ldg(&g_dst[e]);
    atomicAdd(&g_acc3[d], __ldg(&g_h3[s]));
}

// ---------------------------------------------------------------- layer 3 (HID -> 1), warp per node

__global__ void layer3_k(const float* __restrict__ b2, const float* __restrict__ W3, int N) {
    int g    = blockIdx.x * blockDim.x + threadIdx.x;
    int node = g >> 5;
    int lane = g & 31;
    if (node >= N) return;
    float d = g_dis[node];
    float v = fmaxf(fmaf(d, g_buf2[(size_t)node * 32 + lane], b2[lane]), 0.f) * W3[lane];
#pragma unroll
    for (int o = 16; o; o >>= 1) v += __shfl_xor_sync(0xffffffffu, v, o);
    if (lane == 0) g_h3[node] = v * d;  // fold dis[src] into h3'
}

__global__ void final_k(const float* __restrict__ b3, float* __restrict__ out, int N) {
    int i = blockIdx.x * blockDim.x + threadIdx.x;
    if (i >= N) return;
    float z = fmaf(g_dis[i], g_acc3[i], b3[0]);
    out[i] = 1.f / (1.f + __expf(-z));
}

// ---------------------------------------------------------------- launch

extern "C" void kernel_launch(void* const* d_in, const int* in_sizes, int n_in,
                              void* d_out, int out_size) {
    const float* x  = (const float*)d_in[0];
    const int*   ei = (const int*)d_in[1];          // int32 (JAX default x64=off)
    const float* W1 = (const float*)d_in[2];
    const float* b1 = (const float*)d_in[3];
    const float* W2 = (const float*)d_in[4];
    const float* b2 = (const float*)d_in[5];
    const float* W3 = (const float*)d_in[6];
    const float* b3 = (const float*)d_in[7];
    float* out = (float*)d_out;

    const int N = in_sizes[0] / 128;
    const int E = in_sizes[1] / 2;

    void *p0, *p1, *p2;
    cudaGetSymbolAddress(&p0, g_buf0);
    cudaGetSymbolAddress(&p1, g_buf1);
    cudaGetSymbolAddress(&p2, g_buf2);
    float* buf0 = (float*)p0;
    float* buf1 = (float*)p1;
    float* buf2 = (float*)p2;
    void* pdis;
    cudaGetSymbolAddress(&pdis, g_dis);
    float* dis = (float*)pdis;

    const int T = 256;
    // prep: degrees + guarded int32 indices + dis
    deg_init_k<<<(N + T - 1) / T, T>>>(N);
    edge_pre_k<<<(E + T - 1) / T, T>>>(ei, E, N);
    dis_k<<<(N + T - 1) / T, T>>>(N);

    const int gemm_blocks = (N + 31) / 32;
    const int n4 = N * 8;                 // N*32 floats / 4
    const long long sthreads = (long long)E * 8;
    const int sblocks = (int)((sthreads + T - 1) / T);

    // layer 1
    gemm_k<128, false><<<gemm_blocks, 64>>>(x, W1, dis, nullptr, buf0, N);
    copy01_k<<<(n4 + T - 1) / T, T>>>(n4);
    scatter_k<<<sblocks, T>>>(buf0, buf1, E);

    // layer 2 (relu + bias + dis fused into GEMM prologue)
    gemm_k<32, true><<<gemm_blocks, 64>>>(buf1, W2, dis, b1, buf0, N);
    copy02_k<<<(n4 + T - 1) / T, T>>>(n4);
    scatter_k<<<sblocks, T>>>(buf0, buf2, E);

    // layer 3
    layer3_k<<<(N * 32 + T - 1) / T, T>>>(b2, W3, N);
    copy3_k<<<(N + T - 1) / T, T>>>(N);
    scatter3_k<<<(E + T - 1) / T, T>>>(E);
    final_k<<<(N + T - 1) / T, T>>>(b3, out, N);
}

// round 8
// speedup vs baseline: 2.0487x; 2.0487x over previous
#include <cuda_runtime.h>
#include <cstdint>

#define NMAX 150016
#define EMAX 2400000
#define SCAN_BLK 1024

__device__ int   g_cnt[NMAX];      // in-degree (real edges only)
__device__ int   g_rp[NMAX];       // CSR row_ptr (exclusive scan of cnt)
__device__ int   g_cur[NMAX];      // fill cursors
__device__ int   g_bsum[1024];
__device__ int   g_boff[1024];
__device__ int   g_csr[EMAX];      // src indices bucketed by dst
__device__ float g_dis[NMAX];
__device__ __align__(16) float g_buf0[NMAX * 32];   // h' (scaled GEMM output)
__device__ __align__(16) float g_buf1[NMAX * 32];   // layer-1 aggregate
__device__ __align__(16) float g_buf2[NMAX * 32];   // layer-2 aggregate
__device__ float g_h3[NMAX];

// ---------------------------------------------------------------- prep

__global__ void cnt_init_k(int N) {
    int i = blockIdx.x * blockDim.x + threadIdx.x;
    if (i < N) g_cnt[i] = 0;
}

__global__ void edge_cnt_k(const int* __restrict__ ei, int E, int N) {
    int e = blockIdx.x * blockDim.x + threadIdx.x;
    if (e >= E) return;
    int d = ei[E + e];
    if ((unsigned)d >= (unsigned)N) d = 0;
    atomicAdd(&g_cnt[d], 1);
}

__global__ void dis_k(int N) {
    int i = blockIdx.x * blockDim.x + threadIdx.x;
    if (i < N) g_dis[i] = rsqrtf((float)(g_cnt[i] + 1));
}

// 3-phase exclusive scan of g_cnt -> g_rp (and g_cur)
__global__ void scan1_k(int N) {
    __shared__ int sh[SCAN_BLK];
    int i = blockIdx.x * SCAN_BLK + threadIdx.x;
    int v = (i < N) ? g_cnt[i] : 0;
    sh[threadIdx.x] = v;
    __syncthreads();
    for (int off = 1; off < SCAN_BLK; off <<= 1) {
        int t = (threadIdx.x >= off) ? sh[threadIdx.x - off] : 0;
        __syncthreads();
        sh[threadIdx.x] += t;
        __syncthreads();
    }
    if (i < N) g_rp[i] = sh[threadIdx.x] - v;   // exclusive
    if (threadIdx.x == SCAN_BLK - 1) g_bsum[blockIdx.x] = sh[threadIdx.x];
}

__global__ void scan2_k(int nb) {
    __shared__ int sh[1024];
    int v = (threadIdx.x < nb) ? g_bsum[threadIdx.x] : 0;
    sh[threadIdx.x] = v;
    __syncthreads();
    for (int off = 1; off < 1024; off <<= 1) {
        int t = (threadIdx.x >= off) ? sh[threadIdx.x - off] : 0;
        __syncthreads();
        sh[threadIdx.x] += t;
        __syncthreads();
    }
    if (threadIdx.x < nb) g_boff[threadIdx.x] = sh[threadIdx.x] - v;  // exclusive
}

__global__ void scan3_k(int N) {
    int i = blockIdx.x * blockDim.x + threadIdx.x;
    if (i < N) {
        int r = g_rp[i] + g_boff[i / SCAN_BLK];
        g_rp[i]  = r;
        g_cur[i] = r;
    }
}

__global__ void fill_k(const int* __restrict__ ei, int E, int N) {
    int e = blockIdx.x * blockDim.x + threadIdx.x;
    if (e >= E) return;
    int s = ei[e];
    int d = ei[E + e];
    if ((unsigned)s >= (unsigned)N) s = 0;
    if ((unsigned)d >= (unsigned)N) d = 0;
    int pos = atomicAdd(&g_cur[d], 1);
    g_csr[pos] = s;
}

// ---------------------------------------------------------------- GEMM (32 out cols)
// 256 threads, tile 128 rows x 32 cols, 4x4 microtile, K chunked by 32.
// PRE: relu(dis[row]*v + bias[col]) on input; epilogue scales row by dis[row].

template <int K, bool PRE>
__global__ void __launch_bounds__(256) gemm_k(
    const float* __restrict__ A, const float* __restrict__ W,
    const float* __restrict__ dis, const float* __restrict__ bias,
    float* __restrict__ out, int M)
{
    __shared__ float ws[K][32];
    __shared__ float xs[128][33];

    const int tid  = threadIdx.x;
    const int row0 = blockIdx.x * 128;
    const int tx = tid & 7;     // col quad
    const int ty = tid >> 3;    // row quad (0..31)

    for (int i = tid; i < K * 8; i += 256)
        ((float4*)ws)[i] = ((const float4*)W)[i];

    float acc[4][4] = {};

    for (int kc = 0; kc < K; kc += 32) {
        __syncthreads();
        // stage 128x32 chunk of A (4 float4 per thread)
        for (int i = tid; i < 1024; i += 256) {
            int r  = i >> 3;
            int c4 = i & 7;
            int row = row0 + r;
            float4 v = make_float4(0.f, 0.f, 0.f, 0.f);
            if (row < M) {
                v = *(const float4*)(A + (size_t)row * K + kc + c4 * 4);
                if (PRE) {
                    float dd  = dis[row];
                    float4 bb = *(const float4*)(bias + kc + c4 * 4);
                    v.x = fmaxf(fmaf(dd, v.x, bb.x), 0.f);
                    v.y = fmaxf(fmaf(dd, v.y, bb.y), 0.f);
                    v.z = fmaxf(fmaf(dd, v.z, bb.z), 0.f);
                    v.w = fmaxf(fmaf(dd, v.w, bb.w), 0.f);
                }
            }
            xs[r][c4 * 4 + 0] = v.x;
            xs[r][c4 * 4 + 1] = v.y;
            xs[r][c4 * 4 + 2] = v.z;
            xs[r][c4 * 4 + 3] = v.w;
        }
        __syncthreads();

#pragma unroll
        for (int k = 0; k < 32; ++k) {
            float4 wv = *(const float4*)&ws[kc + k][4 * tx];
            float xr0 = xs[4 * ty + 0][k];
            float xr1 = xs[4 * ty + 1][k];
            float xr2 = xs[4 * ty + 2][k];
            float xr3 = xs[4 * ty + 3][k];
            acc[0][0] = fmaf(xr0, wv.x, acc[0][0]);
            acc[0][1] = fmaf(xr0, wv.y, acc[0][1]);
            acc[0][2] = fmaf(xr0, wv.z, acc[0][2]);
            acc[0][3] = fmaf(xr0, wv.w, acc[0][3]);
            acc[1][0] = fmaf(xr1, wv.x, acc[1][0]);
            acc[1][1] = fmaf(xr1, wv.y, acc[1][1]);
            acc[1][2] = fmaf(xr1, wv.z, acc[1][2]);
            acc[1][3] = fmaf(xr1, wv.w, acc[1][3]);
            acc[2][0] = fmaf(xr2, wv.x, acc[2][0]);
            acc[2][1] = fmaf(xr2, wv.y, acc[2][1]);
            acc[2][2] = fmaf(xr2, wv.z, acc[2][2]);
            acc[2][3] = fmaf(xr2, wv.w, acc[2][3]);
            acc[3][0] = fmaf(xr3, wv.x, acc[3][0]);
            acc[3][1] = fmaf(xr3, wv.y, acc[3][1]);
            acc[3][2] = fmaf(xr3, wv.z, acc[3][2]);
            acc[3][3] = fmaf(xr3, wv.w, acc[3][3]);
        }
    }

#pragma unroll
    for (int i = 0; i < 4; ++i) {
        int row = row0 + 4 * ty + i;
        if (row < M) {
            float d = dis[row];
            float4 o = make_float4(acc[i][0] * d, acc[i][1] * d,
                                   acc[i][2] * d, acc[i][3] * d);
            *(float4*)(out + (size_t)row * 32 + 4 * tx) = o;
        }
    }
}

// ---------------------------------------------------------------- aggregate (warp per node)
// acc initialized with self term h'[node]; per in-edge gather h'[src] (coalesced 128B line).

__global__ void __launch_bounds__(256) agg_k(
    const float* __restrict__ h, float* __restrict__ out, int N)
{
    int w    = (blockIdx.x * blockDim.x + threadIdx.x) >> 5;
    int lane = threadIdx.x & 31;
    if (w >= N) return;
    const float* hp = h + lane;
    int beg = g_rp[w];
    int cnt = g_cnt[w];
    float acc = hp[(size_t)w * 32];
    int j = 0;
    for (; j + 4 <= cnt; j += 4) {
        int s0 = __ldg(&g_csr[beg + j + 0]);
        int s1 = __ldg(&g_csr[beg + j + 1]);
        int s2 = __ldg(&g_csr[beg + j + 2]);
        int s3 = __ldg(&g_csr[beg + j + 3]);
        float v0 = __ldg(&hp[(size_t)s0 * 32]);
        float v1 = __ldg(&hp[(size_t)s1 * 32]);
        float v2 = __ldg(&hp[(size_t)s2 * 32]);
        float v3 = __ldg(&hp[(size_t)s3 * 32]);
        acc += (v0 + v1) + (v2 + v3);
    }
    for (; j < cnt; ++j) {
        int s = __ldg(&g_csr[beg + j]);
        acc += __ldg(&hp[(size_t)s * 32]);
    }
    out[(size_t)w * 32 + lane] = acc;
}

// ---------------------------------------------------------------- layer 3 (HID -> 1)

__global__ void layer3_k(const float* __restrict__ b2, const float* __restrict__ W3, int N) {
    int g    = blockIdx.x * blockDim.x + threadIdx.x;
    int node = g >> 5;
    int lane = g & 31;
    if (node >= N) return;
    float d = g_dis[node];
    float v = fmaxf(fmaf(d, g_buf2[(size_t)node * 32 + lane], b2[lane]), 0.f) * W3[lane];
#pragma unroll
    for (int o = 16; o; o >>= 1) v += __shfl_xor_sync(0xffffffffu, v, o);
    if (lane == 0) g_h3[node] = v * d;  // h3' = h3 * dis[src]
}

// fused aggregate + sigmoid: lanes split the edge list, butterfly reduce.
__global__ void __launch_bounds__(256) agg3_final_k(
    const float* __restrict__ b3, float* __restrict__ out, int N)
{
    int w    = (blockIdx.x * blockDim.x + threadIdx.x) >> 5;
    int lane = threadIdx.x & 31;
    if (w >= N) return;
    int beg = g_rp[w];
    int cnt = g_cnt[w];
    float acc = 0.f;
    for (int j = lane; j < cnt; j += 32)
        acc += __ldg(&g_h3[__ldg(&g_csr[beg + j])]);
#pragma unroll
    for (int o = 16; o; o >>= 1) acc += __shfl_xor_sync(0xffffffffu, acc, o);
    if (lane == 0) {
        float z = fmaf(g_dis[w], g_h3[w] + acc, b3[0]);
        out[w] = 1.f / (1.f + __expf(-z));
    }
}

// ---------------------------------------------------------------- launch

extern "C" void kernel_launch(void* const* d_in, const int* in_sizes, int n_in,
                              void* d_out, int out_size) {
    const float* x  = (const float*)d_in[0];
    const int*   ei = (const int*)d_in[1];          // int32
    const float* W1 = (const float*)d_in[2];
    const float* b1 = (const float*)d_in[3];
    const float* W2 = (const float*)d_in[4];
    const float* b2 = (const float*)d_in[5];
    const float* W3 = (const float*)d_in[6];
    const float* b3 = (const float*)d_in[7];
    float* out = (float*)d_out;

    const int N = in_sizes[0] / 128;
    const int E = in_sizes[1] / 2;

    void *p0, *p1, *p2, *pdis;
    cudaGetSymbolAddress(&p0, g_buf0);
    cudaGetSymbolAddress(&p1, g_buf1);
    cudaGetSymbolAddress(&p2, g_buf2);
    cudaGetSymbolAddress(&pdis, g_dis);
    float* buf0 = (float*)p0;
    float* buf1 = (float*)p1;
    float* buf2 = (float*)p2;
    float* dis  = (float*)pdis;

    const int T = 256;
    const int nb = (N + SCAN_BLK - 1) / SCAN_BLK;

    // prep: degree count, dis, CSR build
    cnt_init_k<<<(N + T - 1) / T, T>>>(N);
    edge_cnt_k<<<(E + T - 1) / T, T>>>(ei, E, N);
    dis_k<<<(N + T - 1) / T, T>>>(N);
    scan1_k<<<nb, SCAN_BLK>>>(N);
    scan2_k<<<1, 1024>>>(nb);
    scan3_k<<<(N + T - 1) / T, T>>>(N);
    fill_k<<<(E + T - 1) / T, T>>>(ei, E, N);

    const int gemm_blocks = (N + 127) / 128;
    const int agg_blocks  = (N * 32 + T - 1) / T;

    // layer 1
    gemm_k<128, false><<<gemm_blocks, 256>>>(x, W1, dis, nullptr, buf0, N);
    agg_k<<<agg_blocks, T>>>(buf0, buf1, N);

    // layer 2 (relu + bias + dis fused into GEMM prologue)
    gemm_k<32, true><<<gemm_blocks, 256>>>(buf1, W2, dis, b1, buf0, N);
    agg_k<<<agg_blocks, T>>>(buf0, buf2, N);

    // layer 3
    layer3_k<<<agg_blocks, T>>>(b2, W3, N);
    agg3_final_k<<<agg_blocks, T>>>(b3, out, N);
}